// round 11
// baseline (speedup 1.0000x reference)
#include <cuda_runtime.h>
#include <cuda_fp16.h>

#define NSTEP 255
typedef unsigned long long u64;

// ---------------- static device scratch (no allocation) ----------------
__device__ __align__(16) __half  g_keys[256 * 512 * 256];   // keys [b][t][u] (prep temp)
__device__ __align__(16) __half  g_keysT[256 * 256 * 512];  // keys [b][u][t]
__device__ __align__(16) __half  g_mem16[256 * 512 * 256];  // memory [b][t][u]
__device__ __align__(16) float   g_w1f[512 * 1024];         // Wa@Wi6 + [Wh;0]
__device__ __align__(16) float   g_waf[512 * 6];            // Wa@Wf
__device__ __align__(16) u64     g_wq4[256 * 64];           // Wq fp16 [k][u4]
__device__ __align__(16) float   g_hc[256 * 512];           // [h | ctx] per row
__device__ __align__(16) float   g_z[4 * 256 * 1024];       // split-K=4 partials
__device__ unsigned g_arrive;
__device__ volatile unsigned g_release;

// ---------------- helpers ----------------
__device__ __forceinline__ __half2 tanh2(__half2 x) {
    unsigned xi = *(unsigned*)&x, yi;
    asm("tanh.approx.f16x2 %0,%1;" : "=r"(yi) : "r"(xi));
    return *(__half2*)&yi;
}
__device__ __forceinline__ float sigm(float x) { return 1.0f / (1.0f + __expf(-x)); }
__device__ __forceinline__ u64 dup2(float w) {
    u64 r; asm("mov.b64 %0,{%1,%1};" : "=l"(r) : "f"(w)); return r;
}
__device__ __forceinline__ u64 fma2(u64 a, u64 b, u64 c) {
    u64 d; asm("fma.rn.f32x2 %0,%1,%2,%3;" : "=l"(d) : "l"(a), "l"(b), "l"(c)); return d;
}
__device__ __forceinline__ float2 up2(u64 a) {
    float2 v; asm("mov.b64 {%0,%1},%2;" : "=f"(v.x), "=f"(v.y) : "l"(a)); return v;
}
__device__ __forceinline__ u64 mkpol_el() {
    u64 p; asm("createpolicy.fractional.L2::evict_last.b64 %0, 1.0;" : "=l"(p)); return p;
}
__device__ __forceinline__ u64 mkpol_ef() {
    u64 p; asm("createpolicy.fractional.L2::evict_first.b64 %0, 1.0;" : "=l"(p)); return p;
}
__device__ __forceinline__ u64 ldg_hint(const void* p, u64 pol) {
    u64 v;
    asm("ld.global.nc.L2::cache_hint.b64 %0, [%1], %2;" : "=l"(v) : "l"(p), "l"(pol));
    return v;
}

// ---------------- prep (exactly 3 kernels; k_loop is launch #6 incl. harness) ----
__global__ void k_p1(const float* __restrict__ mem, const float* __restrict__ Wm) {
    __shared__ float As[32 * 17];
    __shared__ float Bs[16 * 64];
    int r0 = blockIdx.x * 32, c0 = blockIdx.y * 64;
    int tid = threadIdx.x, tx = tid & 15, ty = tid >> 4;
    float acc[2][4] = {};
    for (int k0 = 0; k0 < 256; k0 += 16) {
#pragma unroll
        for (int it = 0; it < 2; it++) {
            int i = tid + it * 256, r = i >> 4, k = i & 15;
            As[r * 17 + k] = mem[(size_t)(r0 + r) * 256 + k0 + k];
        }
#pragma unroll
        for (int it = 0; it < 4; it++) {
            int i = tid + it * 256, k = i >> 6, c = i & 63;
            Bs[k * 64 + c] = Wm[(size_t)(k0 + k) * 256 + c0 + c];
        }
        __syncthreads();
#pragma unroll
        for (int k = 0; k < 16; k++) {
            float4 b4 = *(float4*)&Bs[k * 64 + tx * 4];
#pragma unroll
            for (int i = 0; i < 2; i++) {
                float a = As[(ty * 2 + i) * 17 + k];
                acc[i][0] += a * b4.x; acc[i][1] += a * b4.y;
                acc[i][2] += a * b4.z; acc[i][3] += a * b4.w;
            }
        }
        __syncthreads();
    }
#pragma unroll
    for (int i = 0; i < 2; i++) {
        size_t r = r0 + ty * 2 + i;
        __half2* d = (__half2*)(g_keys + r * 256 + c0 + tx * 4);
        d[0] = __floats2half2_rn(acc[i][0], acc[i][1]);
        d[1] = __floats2half2_rn(acc[i][2], acc[i][3]);
    }
}

__global__ void k_p2(const float* __restrict__ mem) {
    __shared__ __half s[64][65];
    int bidx = blockIdx.x, tid = threadIdx.x;
    if (bidx < 8192) {
        int b = bidx >> 5, rem = bidx & 31;
        int t0 = (rem & 7) * 64, u0 = (rem >> 3) * 64;
#pragma unroll
        for (int i = 0; i < 8; i++) {
            int idx = tid + i * 256;
            int t_loc = idx >> 5, u2 = idx & 31;
            __half2 v = *(const __half2*)(g_keys + ((size_t)(b * 512 + t0 + t_loc)) * 256 + u0 + u2 * 2);
            s[u2 * 2][t_loc] = __low2half(v);
            s[u2 * 2 + 1][t_loc] = __high2half(v);
        }
        __syncthreads();
#pragma unroll
        for (int i = 0; i < 8; i++) {
            int idx = tid + i * 256;
            int u_loc = idx >> 5, t2 = idx & 31;
            __half2 v = __halves2half2(s[u_loc][t2 * 2], s[u_loc][t2 * 2 + 1]);
            *(__half2*)(g_keysT + ((size_t)(b * 256 + u0 + u_loc)) * 512 + t0 + t2 * 2) = v;
        }
    } else {
        size_t i = ((size_t)(bidx - 8192) * 256 + tid) * 8;
        float4 f0 = *(const float4*)(mem + i);
        float4 f1 = *(const float4*)(mem + i + 4);
        __half2* d = (__half2*)(g_mem16 + i);
        d[0] = __floats2half2_rn(f0.x, f0.y); d[1] = __floats2half2_rn(f0.z, f0.w);
        d[2] = __floats2half2_rn(f1.x, f1.y); d[3] = __floats2half2_rn(f1.z, f1.w);
    }
}

__global__ void k_p3(const float* __restrict__ Wa, const float* __restrict__ Wi,
                     const float* __restrict__ Wh, const float* __restrict__ Wq,
                     const float* __restrict__ Wf, const float* __restrict__ eh) {
    __shared__ float As[32 * 17];
    __shared__ float Bs[16 * 64];
    int bidx = blockIdx.x, tid = threadIdx.x;
    if (bidx < 256) {
        int r0 = (bidx >> 4) * 32, c0 = (bidx & 15) * 64;
        int tx = tid & 15, ty = tid >> 4;
        const float* Wi6 = Wi + 6 * 1024;
        float acc[2][4] = {};
        for (int k0 = 0; k0 < 256; k0 += 16) {
#pragma unroll
            for (int it = 0; it < 2; it++) {
                int i = tid + it * 256, r = i >> 4, k = i & 15;
                As[r * 17 + k] = Wa[(size_t)(r0 + r) * 256 + k0 + k];
            }
#pragma unroll
            for (int it = 0; it < 4; it++) {
                int i = tid + it * 256, k = i >> 6, c = i & 63;
                Bs[k * 64 + c] = Wi6[(size_t)(k0 + k) * 1024 + c0 + c];
            }
            __syncthreads();
#pragma unroll
            for (int k = 0; k < 16; k++) {
                float4 b4 = *(float4*)&Bs[k * 64 + tx * 4];
#pragma unroll
                for (int i = 0; i < 2; i++) {
                    float a = As[(ty * 2 + i) * 17 + k];
                    acc[i][0] += a * b4.x; acc[i][1] += a * b4.y;
                    acc[i][2] += a * b4.z; acc[i][3] += a * b4.w;
                }
            }
            __syncthreads();
        }
#pragma unroll
        for (int i = 0; i < 2; i++) {
            int row = r0 + ty * 2 + i;
            float4 o = make_float4(acc[i][0], acc[i][1], acc[i][2], acc[i][3]);
            if (row < 256) {
                float4 wh = *(const float4*)&Wh[(size_t)row * 1024 + c0 + tx * 4];
                o.x += wh.x; o.y += wh.y; o.z += wh.z; o.w += wh.w;
            }
            *(float4*)&g_w1f[(size_t)row * 1024 + c0 + tx * 4] = o;
        }
    } else {
        int rb = bidx - 256;
        if (rb < 64) {
            int i = rb * 256 + tid;  // < 16384
            int k = i >> 6, u4 = i & 63;
            __half2 lo = __floats2half2_rn(Wq[k * 256 + u4 * 4], Wq[k * 256 + u4 * 4 + 1]);
            __half2 hi = __floats2half2_rn(Wq[k * 256 + u4 * 4 + 2], Wq[k * 256 + u4 * 4 + 3]);
            u64 v; ((__half2*)&v)[0] = lo; ((__half2*)&v)[1] = hi;
            g_wq4[k * 64 + u4] = v;
        } else if (rb < 76) {
            int o = (rb - 64) * 256 + tid;
            if (o < 512 * 6) {
                int r = o / 6, v = o - r * 6;
                float acc = 0.0f;
#pragma unroll 4
                for (int k = 0; k < 256; k++) acc += Wa[r * 256 + k] * Wf[k * 6 + v];
                g_waf[o] = acc;
            }
        } else {
            int b = rb - 76;  // 0..255
            g_hc[b * 512 + tid] = eh[b * 256 + tid];  // h0
            g_hc[b * 512 + 256 + tid] = 0.0f;         // ctx0 (unused at t=0)
            if (b == 0 && tid == 0) { g_arrive = 0; g_release = 0; }
        }
    }
}

// ---------------- persistent loop kernel (512 threads/block) ----------------
__device__ __forceinline__ void gsync(unsigned& ep) {
    __threadfence();
    __syncthreads();
    ep++;
    if (threadIdx.x == 0) {
        unsigned prev = atomicAdd(&g_arrive, 1u);
        if (prev == ep * 256u - 1u) g_release = ep;
        else while (g_release < ep) {}
    }
    __syncthreads();
}

// dynamic smem = 41984B: phase A As[128*66]f (33792) + Bs2[16*64]u64 (8192)
// phase BC overlays: s_hc 0 | spqh 2048 | sc 3072 | s_z 5120 | s_part 9216 |
//                    sp_pq 17408 | sred 25600..41983
__global__ void __launch_bounds__(512, 2)
k_loop(const int* __restrict__ ids, const float* __restrict__ ec,
       const float* __restrict__ Wi, const float* __restrict__ Wh,
       const float* __restrict__ bias, const float* __restrict__ vv,
       const float* __restrict__ bf, float* __restrict__ out) {
    extern __shared__ __align__(16) unsigned char s_un[];
    __shared__ __align__(16) float   s_waf[512 * 6];
    __shared__ __align__(16) float   s_bias[1024];
    __shared__ __align__(16) __half2 s_vh[256];
    __shared__ float s_red16[16];

    float*   As     = (float*)s_un;              // A: [128][66]
    u64*     Bs2    = (u64*)(s_un + 33792);      // A: [16][64]
    float*   s_hc   = (float*)s_un;              // 512
    __half2* spqh   = (__half2*)(s_un + 2048);   // 256
    float*   sc     = (float*)(s_un + 3072);     // 512
    float*   s_z    = (float*)(s_un + 5120);     // 1024
    float*   s_part = (float*)(s_un + 9216);     // 2048
    float*   sp_pq  = (float*)(s_un + 17408);    // 2048
    float*   sred   = (float*)(s_un + 25600);    // 4096

    const int tid = threadIdx.x, b = blockIdx.x;
    const int lane = tid & 31, w = tid >> 5;       // 16 warps
    const u64 pol_el = mkpol_el(), pol_ef = mkpol_ef();

    float creg = (tid < 256) ? ec[b * 256 + tid] : 0.0f;
    for (int i = tid; i < 3072; i += 512) s_waf[i] = g_waf[i];
    for (int i = tid; i < 1024; i += 512) s_bias[i] = bias[i];
    if (tid < 256) s_vh[tid] = __half2half2(__float2half_rn(vv[tid]));
    __syncthreads();

    // phase-A mapping: split-K=4, tile 64x64
    const int kb = b >> 6, tl = b & 63;
    const int ar0 = (tl >> 4) * 64, ac0 = (tl & 15) * 64, kbase = kb * 128;
    float* zp = g_z + (size_t)kb * 262144;
    const int tx = tid & 15, tyy = tid >> 4;  // col-quad, row-pair (0..31)

    unsigned ep = 0;

    for (int t = 0; t < NSTEP; t++) {
        // ===== phase A: z partial = [h,ctx] @ W1' (t=0: h@Wh, only kb<2) =====
        if (t > 0 || kb < 2) {
            const float* Bsrc = (t == 0) ? (Wh + (size_t)kbase * 1024)
                                         : (g_w1f + (size_t)kbase * 1024);
#pragma unroll
            for (int it = 0; it < 4; it++) {
                int idx = tid + it * 512;
                int row = idx >> 5, kq = idx & 31;
                float4 v = __ldcg((const float4*)&g_hc[(size_t)(ar0 + row) * 512 + kbase + kq * 4]);
                As[(kq * 4 + 0) * 66 + row] = v.x;
                As[(kq * 4 + 1) * 66 + row] = v.y;
                As[(kq * 4 + 2) * 66 + row] = v.z;
                As[(kq * 4 + 3) * 66 + row] = v.w;
            }
            __syncthreads();
            u64 acc[4] = {0, 0, 0, 0};
            for (int k0 = 0; k0 < 128; k0 += 16) {
#pragma unroll
                for (int it = 0; it < 2; it++) {
                    int i = tid + it * 512;
                    int kk = i >> 6, c = i & 63;
                    Bs2[kk * 64 + (c & 3) * 16 + (c >> 2)] =
                        dup2(__ldg(&Bsrc[(size_t)(k0 + kk) * 1024 + ac0 + c]));
                }
                __syncthreads();
#pragma unroll
                for (int kk = 0; kk < 16; kk++) {
                    u64 a = *(const u64*)&As[(k0 + kk) * 66 + tyy * 2];
                    acc[0] = fma2(a, Bs2[kk * 64 + tx], acc[0]);
                    acc[1] = fma2(a, Bs2[kk * 64 + 16 + tx], acc[1]);
                    acc[2] = fma2(a, Bs2[kk * 64 + 32 + tx], acc[2]);
                    acc[3] = fma2(a, Bs2[kk * 64 + 48 + tx], acc[3]);
                }
                __syncthreads();
            }
            float2 p0 = up2(acc[0]), p1 = up2(acc[1]), p2 = up2(acc[2]), p3 = up2(acc[3]);
            size_t base = (size_t)(ar0 + tyy * 2) * 1024 + ac0 + tx * 4;
            *(float4*)&zp[base]        = make_float4(p0.x, p1.x, p2.x, p3.x);
            *(float4*)&zp[base + 1024] = make_float4(p0.y, p1.y, p2.y, p3.y);
        }
        gsync(ep);

        // ===== phase BC (block = batch row b) =====
        {
            // --- gate pre-activations: 2 per thread ---
            int id = ids[b * 256 + t];
            const float* wr = Wi + (size_t)id * 1024;
#pragma unroll
            for (int j = 0; j < 2; j++) {
                int gi = tid + j * 512;
                const float* z0 = g_z + (size_t)b * 1024 + gi;
                float zs = __ldcg(z0) + __ldcg(z0 + 262144);
                if (t > 0) zs += __ldcg(z0 + 524288) + __ldcg(z0 + 786432);
                s_z[gi] = zs + wr[gi] + s_bias[gi];
            }
            __syncthreads();
            if (tid < 256) {
                float zi = s_z[tid], zf = s_z[256 + tid], zg = s_z[512 + tid], zo = s_z[768 + tid];
                float cn = sigm(zf) * creg + sigm(zi) * tanhf(zg);
                float hn = sigm(zo) * tanhf(cn);
                creg = cn;
                s_hc[tid] = hn;
                g_hc[b * 512 + tid] = hn;
            }
            __syncthreads();

            // --- pq = h @ Wq (fp16 u64-packed, k-split 8) ---
            {
                int ks = tid >> 6, u4 = tid & 63;
                const u64* wq = g_wq4 + (size_t)ks * 32 * 64 + u4;
                float4 a = {0, 0, 0, 0};
#pragma unroll 8
                for (int kk = 0; kk < 32; kk++) {
                    float hk = s_hc[ks * 32 + kk];
                    u64 raw = __ldg(wq + (size_t)kk * 64);
                    float2 lo = __half22float2(((__half2*)&raw)[0]);
                    float2 hi = __half22float2(((__half2*)&raw)[1]);
                    a.x = fmaf(hk, lo.x, a.x); a.y = fmaf(hk, lo.y, a.y);
                    a.z = fmaf(hk, hi.x, a.z); a.w = fmaf(hk, hi.y, a.w);
                }
                *(float4*)&sp_pq[ks * 256 + u4 * 4] = a;
            }
            __syncthreads();
            if (tid < 256) {
                float pqv = 0.0f;
#pragma unroll
                for (int i = 0; i < 8; i++) pqv += sp_pq[i * 256 + tid];
                spqh[tid] = __half2half2(__float2half_rn(pqv));
            }
            __syncthreads();

            // --- scores: chunked-fp16 accumulate over transposed keys ---
            {
                int uh = tid >> 7, tq = tid & 127;
                const u64* KT = (const u64*)g_keysT + (size_t)(b * 256 + uh * 64) * 128 + tq;
                const __half2* pqh = spqh + uh * 64;
                const __half2* vh = s_vh + uh * 64;
                float4 facc = {0, 0, 0, 0};
#pragma unroll
                for (int ch = 0; ch < 4; ch++) {
                    __half2 a01 = __float2half2_rn(0.0f), a23 = __float2half2_rn(0.0f);
#pragma unroll
                    for (int q = 0; q < 16; q++) {
                        int uo = ch * 16 + q;
                        u64 raw = ldg_hint(KT + (size_t)uo * 128, pol_el);
                        __half2 p2 = pqh[uo], v2 = vh[uo];
                        __half2 t01 = tanh2(__hadd2(((__half2*)&raw)[0], p2));
                        __half2 t23 = tanh2(__hadd2(((__half2*)&raw)[1], p2));
                        a01 = __hfma2(t01, v2, a01);
                        a23 = __hfma2(t23, v2, a23);
                    }
                    float2 f01 = __half22float2(a01), f23 = __half22float2(a23);
                    facc.x += f01.x; facc.y += f01.y; facc.z += f23.x; facc.w += f23.y;
                }
                *(float4*)&s_part[uh * 512 + tq * 4] = facc;
            }
            __syncthreads();

            // --- softmax over 512 scores (no max-sub; |score| <= ~10) ---
            float rawsc = s_part[tid] + s_part[512 + tid] +
                          s_part[1024 + tid] + s_part[1536 + tid];
            float e = __expf(rawsc);
            sc[tid] = e;
            float ss = e;
#pragma unroll
            for (int o = 16; o; o >>= 1) ss += __shfl_down_sync(~0u, ss, o);
            if (!lane) s_red16[w] = ss;
            __syncthreads();
            float tot = 0.0f;
#pragma unroll
            for (int i = 0; i < 16; i++) tot += s_red16[i];
            float inv = 1.0f / tot;

            // --- context: 16 warps x 32 rows, fp32 accumulate ---
            {
                float4 a0 = {0, 0, 0, 0}, a1 = {0, 0, 0, 0};
                const u64* Mb = (const u64*)g_mem16 + (size_t)b * 512 * 64;
#pragma unroll 4
                for (int tt = w * 32; tt < w * 32 + 32; tt++) {
                    float p = sc[tt];
                    u64 q0 = ldg_hint(Mb + (size_t)tt * 64 + lane, pol_ef);
                    u64 q1 = ldg_hint(Mb + (size_t)tt * 64 + 32 + lane, pol_ef);
                    float2 x0 = __half22float2(((__half2*)&q0)[0]);
                    float2 x1 = __half22float2(((__half2*)&q0)[1]);
                    float2 y0 = __half22float2(((__half2*)&q1)[0]);
                    float2 y1 = __half22float2(((__half2*)&q1)[1]);
                    a0.x += p * x0.x; a0.y += p * x0.y; a0.z += p * x1.x; a0.w += p * x1.y;
                    a1.x += p * y0.x; a1.y += p * y0.y; a1.z += p * y1.x; a1.w += p * y1.y;
                }
                *(float4*)&sred[w * 256 + lane * 4] = a0;
                *(float4*)&sred[w * 256 + 128 + lane * 4] = a1;
            }
            __syncthreads();
            if (tid < 256) {
                float ctxv = 0.0f;
#pragma unroll
                for (int i = 0; i < 16; i++) ctxv += sred[i * 256 + tid];
                ctxv *= inv;
                s_hc[256 + tid] = ctxv;
                g_hc[b * 512 + 256 + tid] = ctxv;
            }
            __syncthreads();

            // --- logits_t = [h,ctx] @ Waf + bf ---
            if (w < 6) {
                float acc = 0.0f;
#pragma unroll
                for (int i = 0; i < 16; i++) {
                    int uu = lane + 32 * i;
                    acc += s_hc[uu] * s_waf[uu * 6 + w];
                }
#pragma unroll
                for (int o = 16; o; o >>= 1) acc += __shfl_down_sync(~0u, acc, o);
                if (!lane) out[((size_t)b * NSTEP + t) * 6 + w] = acc + bf[w];
            }
        }
        gsync(ep);
    }
}

// ---------------- launch ----------------
extern "C" void kernel_launch(void* const* d_in, const int* in_sizes, int n_in,
                              void* d_out, int out_size) {
    const int*   ids  = (const int*)d_in[0];
    const float* mem  = (const float*)d_in[1];
    const float* eh   = (const float*)d_in[2];
    const float* ec   = (const float*)d_in[3];
    const float* Wi   = (const float*)d_in[4];
    const float* Wh   = (const float*)d_in[5];
    const float* bias = (const float*)d_in[6];
    const float* Wm   = (const float*)d_in[7];
    const float* Wq   = (const float*)d_in[8];
    const float* vv   = (const float*)d_in[9];
    const float* Wa   = (const float*)d_in[10];
    const float* Wf   = (const float*)d_in[11];
    const float* bf   = (const float*)d_in[12];
    float* out = (float*)d_out;

    static int smem_set = 0;
    if (!smem_set) {
        cudaFuncSetAttribute(k_loop, cudaFuncAttributeMaxDynamicSharedMemorySize, 41984);
        smem_set = 1;
    }

    k_p1<<<dim3(4096, 4), 256>>>(mem, Wm);
    k_p2<<<24576, 256>>>(mem);
    k_p3<<<588, 256>>>(Wa, Wi, Wh, Wq, Wf, eh);
    k_loop<<<256, 512, 41984>>>(ids, ec, Wi, Wh, bias, vv, bf, out);
}

// round 12
// speedup vs baseline: 1.4392x; 1.4392x over previous
#include <cuda_runtime.h>
#include <cuda_fp16.h>

#define NSTEP 255
typedef unsigned long long u64;

// ---------------- static device scratch (no allocation) ----------------
__device__ __align__(16) __half  g_keys[256 * 512 * 256];   // keys [b][t][u] (prep temp)
__device__ __align__(16) __half  g_keysT[256 * 256 * 512];  // keys [b][u][t]
__device__ __align__(16) __half  g_mem16[256 * 512 * 256];  // memory [b][t][u]
__device__ __align__(16) float   g_w1f[512 * 1024];         // Wa@Wi6 + [Wh;0]
__device__ __align__(16) float   g_waf[512 * 6];            // Wa@Wf
__device__ __align__(16) u64     g_wq4[256 * 64];           // Wq fp16 [k][u4]
__device__ __align__(16) float   g_hc[256 * 512];           // [h | ctx] per row
__device__ __align__(16) float   g_z[8 * 256 * 1024];       // split-K=8 partials
__device__ unsigned g_cz[2];    // z-ready counters per 128-row group
__device__ unsigned g_chc[2];   // hc-ready counters per 128-row group

// ---------------- helpers ----------------
__device__ __forceinline__ __half2 tanh2(__half2 x) {
    unsigned xi = *(unsigned*)&x, yi;
    asm("tanh.approx.f16x2 %0,%1;" : "=r"(yi) : "r"(xi));
    return *(__half2*)&yi;
}
__device__ __forceinline__ float sigm(float x) { return 1.0f / (1.0f + __expf(-x)); }
__device__ __forceinline__ u64 dup2(float w) {
    u64 r; asm("mov.b64 %0,{%1,%1};" : "=l"(r) : "f"(w)); return r;
}
__device__ __forceinline__ u64 fma2(u64 a, u64 b, u64 c) {
    u64 d; asm("fma.rn.f32x2 %0,%1,%2,%3;" : "=l"(d) : "l"(a), "l"(b), "l"(c)); return d;
}
__device__ __forceinline__ float2 up2(u64 a) {
    float2 v; asm("mov.b64 {%0,%1},%2;" : "=f"(v.x), "=f"(v.y) : "l"(a)); return v;
}
__device__ __forceinline__ u64 mkpol_el() {
    u64 p; asm("createpolicy.fractional.L2::evict_last.b64 %0, 1.0;" : "=l"(p)); return p;
}
__device__ __forceinline__ u64 mkpol_ef() {
    u64 p; asm("createpolicy.fractional.L2::evict_first.b64 %0, 1.0;" : "=l"(p)); return p;
}
__device__ __forceinline__ u64 ldg_hint(const void* p, u64 pol) {
    u64 v;
    asm("ld.global.nc.L2::cache_hint.b64 %0, [%1], %2;" : "=l"(v) : "l"(p), "l"(pol));
    return v;
}

// ---------------- prep (exactly 3 kernels) ----------------
__global__ void k_p1(const float* __restrict__ mem, const float* __restrict__ Wm) {
    __shared__ float As[32 * 17];
    __shared__ float Bs[16 * 64];
    int r0 = blockIdx.x * 32, c0 = blockIdx.y * 64;
    int tid = threadIdx.x, tx = tid & 15, ty = tid >> 4;
    float acc[2][4] = {};
    for (int k0 = 0; k0 < 256; k0 += 16) {
#pragma unroll
        for (int it = 0; it < 2; it++) {
            int i = tid + it * 256, r = i >> 4, k = i & 15;
            As[r * 17 + k] = mem[(size_t)(r0 + r) * 256 + k0 + k];
        }
#pragma unroll
        for (int it = 0; it < 4; it++) {
            int i = tid + it * 256, k = i >> 6, c = i & 63;
            Bs[k * 64 + c] = Wm[(size_t)(k0 + k) * 256 + c0 + c];
        }
        __syncthreads();
#pragma unroll
        for (int k = 0; k < 16; k++) {
            float4 b4 = *(float4*)&Bs[k * 64 + tx * 4];
#pragma unroll
            for (int i = 0; i < 2; i++) {
                float a = As[(ty * 2 + i) * 17 + k];
                acc[i][0] += a * b4.x; acc[i][1] += a * b4.y;
                acc[i][2] += a * b4.z; acc[i][3] += a * b4.w;
            }
        }
        __syncthreads();
    }
#pragma unroll
    for (int i = 0; i < 2; i++) {
        size_t r = r0 + ty * 2 + i;
        __half2* d = (__half2*)(g_keys + r * 256 + c0 + tx * 4);
        d[0] = __floats2half2_rn(acc[i][0], acc[i][1]);
        d[1] = __floats2half2_rn(acc[i][2], acc[i][3]);
    }
}

__global__ void k_p2(const float* __restrict__ mem) {
    __shared__ __half s[64][65];
    int bidx = blockIdx.x, tid = threadIdx.x;
    if (bidx < 8192) {
        int b = bidx >> 5, rem = bidx & 31;
        int t0 = (rem & 7) * 64, u0 = (rem >> 3) * 64;
#pragma unroll
        for (int i = 0; i < 8; i++) {
            int idx = tid + i * 256;
            int t_loc = idx >> 5, u2 = idx & 31;
            __half2 v = *(const __half2*)(g_keys + ((size_t)(b * 512 + t0 + t_loc)) * 256 + u0 + u2 * 2);
            s[u2 * 2][t_loc] = __low2half(v);
            s[u2 * 2 + 1][t_loc] = __high2half(v);
        }
        __syncthreads();
#pragma unroll
        for (int i = 0; i < 8; i++) {
            int idx = tid + i * 256;
            int u_loc = idx >> 5, t2 = idx & 31;
            __half2 v = __halves2half2(s[u_loc][t2 * 2], s[u_loc][t2 * 2 + 1]);
            *(__half2*)(g_keysT + ((size_t)(b * 256 + u0 + u_loc)) * 512 + t0 + t2 * 2) = v;
        }
    } else {
        size_t i = ((size_t)(bidx - 8192) * 256 + tid) * 8;
        float4 f0 = *(const float4*)(mem + i);
        float4 f1 = *(const float4*)(mem + i + 4);
        __half2* d = (__half2*)(g_mem16 + i);
        d[0] = __floats2half2_rn(f0.x, f0.y); d[1] = __floats2half2_rn(f0.z, f0.w);
        d[2] = __floats2half2_rn(f1.x, f1.y); d[3] = __floats2half2_rn(f1.z, f1.w);
    }
}

__global__ void k_p3(const float* __restrict__ Wa, const float* __restrict__ Wi,
                     const float* __restrict__ Wh, const float* __restrict__ Wq,
                     const float* __restrict__ Wf, const float* __restrict__ eh) {
    __shared__ float As[32 * 17];
    __shared__ float Bs[16 * 64];
    int bidx = blockIdx.x, tid = threadIdx.x;
    if (bidx < 256) {
        int r0 = (bidx >> 4) * 32, c0 = (bidx & 15) * 64;
        int tx = tid & 15, ty = tid >> 4;
        const float* Wi6 = Wi + 6 * 1024;
        float acc[2][4] = {};
        for (int k0 = 0; k0 < 256; k0 += 16) {
#pragma unroll
            for (int it = 0; it < 2; it++) {
                int i = tid + it * 256, r = i >> 4, k = i & 15;
                As[r * 17 + k] = Wa[(size_t)(r0 + r) * 256 + k0 + k];
            }
#pragma unroll
            for (int it = 0; it < 4; it++) {
                int i = tid + it * 256, k = i >> 6, c = i & 63;
                Bs[k * 64 + c] = Wi6[(size_t)(k0 + k) * 1024 + c0 + c];
            }
            __syncthreads();
#pragma unroll
            for (int k = 0; k < 16; k++) {
                float4 b4 = *(float4*)&Bs[k * 64 + tx * 4];
#pragma unroll
                for (int i = 0; i < 2; i++) {
                    float a = As[(ty * 2 + i) * 17 + k];
                    acc[i][0] += a * b4.x; acc[i][1] += a * b4.y;
                    acc[i][2] += a * b4.z; acc[i][3] += a * b4.w;
                }
            }
            __syncthreads();
        }
#pragma unroll
        for (int i = 0; i < 2; i++) {
            int row = r0 + ty * 2 + i;
            float4 o = make_float4(acc[i][0], acc[i][1], acc[i][2], acc[i][3]);
            if (row < 256) {
                float4 wh = *(const float4*)&Wh[(size_t)row * 1024 + c0 + tx * 4];
                o.x += wh.x; o.y += wh.y; o.z += wh.z; o.w += wh.w;
            }
            *(float4*)&g_w1f[(size_t)row * 1024 + c0 + tx * 4] = o;
        }
    } else {
        int rb = bidx - 256;
        if (rb < 64) {
            int i = rb * 256 + tid;  // < 16384
            int k = i >> 6, u4 = i & 63;
            __half2 lo = __floats2half2_rn(Wq[k * 256 + u4 * 4], Wq[k * 256 + u4 * 4 + 1]);
            __half2 hi = __floats2half2_rn(Wq[k * 256 + u4 * 4 + 2], Wq[k * 256 + u4 * 4 + 3]);
            u64 v; ((__half2*)&v)[0] = lo; ((__half2*)&v)[1] = hi;
            g_wq4[k * 64 + u4] = v;
        } else if (rb < 76) {
            int o = (rb - 64) * 256 + tid;
            if (o < 512 * 6) {
                int r = o / 6, v = o - r * 6;
                float acc = 0.0f;
#pragma unroll 4
                for (int k = 0; k < 256; k++) acc += Wa[r * 256 + k] * Wf[k * 6 + v];
                g_waf[o] = acc;
            }
        } else {
            int b = rb - 76;  // 0..255
            g_hc[b * 512 + tid] = eh[b * 256 + tid];  // h0
            g_hc[b * 512 + 256 + tid] = 0.0f;         // ctx0 (unused at t=0)
            if (b == 0 && tid < 2) { g_cz[tid] = 0; g_chc[tid] = 0; }
        }
    }
}

// ---------------- persistent loop kernel (256 threads/block) ----------------
// dynamic smem = 41472B: phase A As[64][130]f (33280) + Bs2[16][64]u64 (8192)
// BC overlays: s_hc 0 | spqh 2048 | sc 3072 | s_part 5120 | sp_pq 9216 | sred 13312
__global__ void __launch_bounds__(256, 2)
k_loop(const int* __restrict__ ids, const float* __restrict__ ec,
       const float* __restrict__ Wi, const float* __restrict__ Wh,
       const float* __restrict__ bias, const float* __restrict__ vv,
       const float* __restrict__ bf, float* __restrict__ out) {
    extern __shared__ __align__(16) unsigned char s_un[];
    __shared__ __align__(16) float   s_waf[512 * 6];
    __shared__ __align__(16) __half2 s_vh[256];
    __shared__ float s_red8[8];

    float*   As     = (float*)s_un;              // A: [64 k][130 rowpad]
    u64*     Bs2    = (u64*)(s_un + 33280);      // A: [16][64]
    float*   s_hc   = (float*)s_un;              // 512
    __half2* spqh   = (__half2*)(s_un + 2048);   // 256
    float*   sc     = (float*)(s_un + 3072);     // 512
    float*   s_part = (float*)(s_un + 5120);     // 1024
    float*   sp_pq  = (float*)(s_un + 9216);     // 1024
    float*   sred   = (float*)(s_un + 13312);    // 2048

    const int tid = threadIdx.x, b = blockIdx.x;
    const int lane = tid & 31, w = tid >> 5;     // 8 warps
    const u64 pol_el = mkpol_el(), pol_ef = mkpol_ef();

    float creg = ec[b * 256 + tid];
    float rb0 = bias[tid], rb1 = bias[256 + tid], rb2 = bias[512 + tid], rb3 = bias[768 + tid];
    for (int i = tid; i < 3072; i += 256) s_waf[i] = g_waf[i];
    s_vh[tid] = __half2half2(__float2half_rn(vv[tid]));
    __syncthreads();

    // group-aligned tile mapping: block X serves row-group X>>7 in BOTH phases
    const int gX = b >> 7;                 // 0 or 1
    const int tl = b & 127;
    const int ac0 = (tl & 15) * 64;        // col tile
    const int kb  = tl >> 4;               // k-slice 0..7
    const int kbase = kb * 64;
    const int ar0 = gX * 128;              // row tile
    float* zp = g_z + (size_t)kb * 262144;
    const int tx = tid & 15, ty = tid >> 4;  // col-quad, row-octet

    for (int t = 0; t < NSTEP; t++) {
        int id = __ldg(&ids[b * 256 + t]);  // early

        // ===== phase A: z partial (128x64 tile, split-K 8) =====
        {
            if (tid == 0 && t > 0) {
                unsigned tgt = (unsigned)t * 128u;
                while (*(volatile unsigned*)&g_chc[gX] < tgt) {}
                __threadfence();
            }
            __syncthreads();
            if (t > 0 || kb < 4) {  // t=0: z = h@Wh only (K 0..255)
                const float* Bsrc = (t == 0) ? (Wh + (size_t)kbase * 1024)
                                             : (g_w1f + (size_t)kbase * 1024);
                // A-slab: 128 rows x 64 k, coalesced, transposed [k][row]
#pragma unroll
                for (int it = 0; it < 8; it++) {
                    int idx = tid + it * 256;
                    int row = idx >> 4, q = idx & 15;
                    float4 v = __ldcg((const float4*)&g_hc[(size_t)(ar0 + row) * 512 + kbase + q * 4]);
                    As[(q * 4 + 0) * 130 + row] = v.x;
                    As[(q * 4 + 1) * 130 + row] = v.y;
                    As[(q * 4 + 2) * 130 + row] = v.z;
                    As[(q * 4 + 3) * 130 + row] = v.w;
                }
                __syncthreads();
                u64 acc[4][4];
#pragma unroll
                for (int j = 0; j < 4; j++)
#pragma unroll
                    for (int c = 0; c < 4; c++) acc[j][c] = 0;
                for (int k0 = 0; k0 < 64; k0 += 16) {
#pragma unroll
                    for (int it = 0; it < 4; it++) {
                        int i = tid + it * 256;
                        int kk = i >> 6, c = i & 63;
                        Bs2[kk * 64 + (c & 3) * 16 + (c >> 2)] =
                            dup2(__ldg(&Bsrc[(size_t)(k0 + kk) * 1024 + ac0 + c]));
                    }
                    __syncthreads();
#pragma unroll
                    for (int kk = 0; kk < 16; kk++) {
                        const float* ak = &As[(k0 + kk) * 130 + ty * 8];
                        u64 a0 = *(const u64*)(ak + 0);
                        u64 a1 = *(const u64*)(ak + 2);
                        u64 a2 = *(const u64*)(ak + 4);
                        u64 a3 = *(const u64*)(ak + 6);
                        u64 b0 = Bs2[kk * 64 + tx];
                        u64 b1 = Bs2[kk * 64 + 16 + tx];
                        u64 b2 = Bs2[kk * 64 + 32 + tx];
                        u64 b3 = Bs2[kk * 64 + 48 + tx];
                        acc[0][0] = fma2(a0, b0, acc[0][0]); acc[0][1] = fma2(a0, b1, acc[0][1]);
                        acc[0][2] = fma2(a0, b2, acc[0][2]); acc[0][3] = fma2(a0, b3, acc[0][3]);
                        acc[1][0] = fma2(a1, b0, acc[1][0]); acc[1][1] = fma2(a1, b1, acc[1][1]);
                        acc[1][2] = fma2(a1, b2, acc[1][2]); acc[1][3] = fma2(a1, b3, acc[1][3]);
                        acc[2][0] = fma2(a2, b0, acc[2][0]); acc[2][1] = fma2(a2, b1, acc[2][1]);
                        acc[2][2] = fma2(a2, b2, acc[2][2]); acc[2][3] = fma2(a2, b3, acc[2][3]);
                        acc[3][0] = fma2(a3, b0, acc[3][0]); acc[3][1] = fma2(a3, b1, acc[3][1]);
                        acc[3][2] = fma2(a3, b2, acc[3][2]); acc[3][3] = fma2(a3, b3, acc[3][3]);
                    }
                    __syncthreads();
                }
#pragma unroll
                for (int j = 0; j < 4; j++) {
                    float2 q0 = up2(acc[j][0]), q1 = up2(acc[j][1]);
                    float2 q2 = up2(acc[j][2]), q3 = up2(acc[j][3]);
                    size_t base = (size_t)(ar0 + ty * 8 + 2 * j) * 1024 + ac0 + tx * 4;
                    *(float4*)&zp[base]        = make_float4(q0.x, q1.x, q2.x, q3.x);
                    *(float4*)&zp[base + 1024] = make_float4(q0.y, q1.y, q2.y, q3.y);
                }
            }
            __syncthreads();
            if (tid == 0) { __threadfence(); atomicAdd(&g_cz[gX], 1u); }
        }

        // ===== phase BC (block = batch row b) =====
        {
            // prefetch gate inputs while polling
            const float* wr = Wi + (size_t)id * 1024;
            float w0 = __ldg(&wr[tid]), w1 = __ldg(&wr[256 + tid]);
            float w2 = __ldg(&wr[512 + tid]), w3 = __ldg(&wr[768 + tid]);
            if (tid == 0) {
                unsigned tgt = (unsigned)(t + 1) * 128u;
                while (*(volatile unsigned*)&g_cz[gX] < tgt) {}
                __threadfence();
            }
            __syncthreads();

            // --- gates ---
            float zi = w0 + rb0, zf = w1 + rb1, zg = w2 + rb2, zo = w3 + rb3;
            const float* zrow = g_z + (size_t)b * 1024 + tid;
            int nsl = (t == 0) ? 4 : 8;
            for (int s = 0; s < nsl; s++) {
                const float* zs = zrow + (size_t)s * 262144;
                zi += __ldcg(zs);       zf += __ldcg(zs + 256);
                zg += __ldcg(zs + 512); zo += __ldcg(zs + 768);
            }
            float cn = sigm(zf) * creg + sigm(zi) * tanhf(zg);
            float hn = sigm(zo) * tanhf(cn);
            creg = cn;
            s_hc[tid] = hn;
            g_hc[b * 512 + tid] = hn;
            __syncthreads();

            // --- pq = h @ Wq (fp16 u64-packed, k-split 4) ---
            {
                int ks = tid >> 6, u4 = tid & 63;
                const u64* wq = g_wq4 + (size_t)ks * 64 * 64 + u4;
                float4 a = {0, 0, 0, 0};
#pragma unroll 8
                for (int kk = 0; kk < 64; kk++) {
                    float hk = s_hc[ks * 64 + kk];
                    u64 raw = __ldg(wq + (size_t)kk * 64);
                    float2 lo = __half22float2(((__half2*)&raw)[0]);
                    float2 hi = __half22float2(((__half2*)&raw)[1]);
                    a.x = fmaf(hk, lo.x, a.x); a.y = fmaf(hk, lo.y, a.y);
                    a.z = fmaf(hk, hi.x, a.z); a.w = fmaf(hk, hi.y, a.w);
                }
                *(float4*)&sp_pq[tid * 4] = a;
            }
            __syncthreads();
            {
                float pqv = sp_pq[tid] + sp_pq[256 + tid] + sp_pq[512 + tid] + sp_pq[768 + tid];
                // sp_pq layout: [ks][u4*4+c] = ks*256 + tid' — reduce across ks
                // (tid indexes u4*4+c directly)
                spqh[tid] = __half2half2(__float2half_rn(pqv));
            }
            __syncthreads();

            // --- scores: chunked-fp16 over transposed keys (L2-resident) ---
            {
                int uh = tid >> 7, tq = tid & 127;
                const u64* KT = (const u64*)g_keysT + ((size_t)(b * 256 + uh * 128)) * 128 + tq;
                const __half2* pqh = spqh + uh * 128;
                const __half2* vh = s_vh + uh * 128;
                float4 facc = {0, 0, 0, 0};
#pragma unroll
                for (int ch = 0; ch < 8; ch++) {
                    __half2 a01 = __float2half2_rn(0.0f), a23 = __float2half2_rn(0.0f);
#pragma unroll
                    for (int q = 0; q < 16; q++) {
                        int uo = ch * 16 + q;
                        u64 raw = ldg_hint(KT + (size_t)uo * 128, pol_el);
                        __half2 p2 = pqh[uo], v2 = vh[uo];
                        __half2 t01 = tanh2(__hadd2(((__half2*)&raw)[0], p2));
                        __half2 t23 = tanh2(__hadd2(((__half2*)&raw)[1], p2));
                        a01 = __hfma2(t01, v2, a01);
                        a23 = __hfma2(t23, v2, a23);
                    }
                    float2 f01 = __half22float2(a01), f23 = __half22float2(a23);
                    facc.x += f01.x; facc.y += f01.y; facc.z += f23.x; facc.w += f23.y;
                }
                *(float4*)&s_part[uh * 512 + tq * 4] = facc;
            }
            __syncthreads();

            // --- softmax (no max-sub; |score| <= sum|v| ~ 10) ---
            float e0 = __expf(s_part[tid] + s_part[512 + tid]);
            float e1 = __expf(s_part[256 + tid] + s_part[768 + tid]);
            float ss = e0 + e1;
#pragma unroll
            for (int o = 16; o; o >>= 1) ss += __shfl_down_sync(~0u, ss, o);
            if (!lane) s_red8[w] = ss;
            sc[tid] = e0; sc[tid + 256] = e1;
            __syncthreads();
            float inv = 1.0f / (s_red8[0] + s_red8[1] + s_red8[2] + s_red8[3] +
                                s_red8[4] + s_red8[5] + s_red8[6] + s_red8[7]);

            // --- context (streaming fp16 memory, fp32 accumulate) ---
            {
                float4 a0 = {0, 0, 0, 0}, a1 = {0, 0, 0, 0};
                const u64* Mb = (const u64*)g_mem16 + (size_t)b * 512 * 64;
#pragma unroll 8
                for (int tt = w * 64; tt < w * 64 + 64; tt++) {
                    float p = sc[tt];
                    u64 q0 = ldg_hint(Mb + (size_t)tt * 64 + lane, pol_ef);
                    u64 q1 = ldg_hint(Mb + (size_t)tt * 64 + 32 + lane, pol_ef);
                    float2 x0 = __half22float2(((__half2*)&q0)[0]);
                    float2 x1 = __half22float2(((__half2*)&q0)[1]);
                    float2 y0 = __half22float2(((__half2*)&q1)[0]);
                    float2 y1 = __half22float2(((__half2*)&q1)[1]);
                    a0.x += p * x0.x; a0.y += p * x0.y; a0.z += p * x1.x; a0.w += p * x1.y;
                    a1.x += p * y0.x; a1.y += p * y0.y; a1.z += p * y1.x; a1.w += p * y1.y;
                }
                *(float4*)&sred[w * 256 + lane * 4] = a0;
                *(float4*)&sred[w * 256 + 128 + lane * 4] = a1;
            }
            __syncthreads();
            {
                float ctxv = 0.0f;
#pragma unroll
                for (int i = 0; i < 8; i++) ctxv += sred[i * 256 + tid];
                ctxv *= inv;
                s_hc[256 + tid] = ctxv;
                g_hc[b * 512 + 256 + tid] = ctxv;
            }
            __syncthreads();
            // signal h,ctx ready for phase A(t+1) of this group
            if (tid == 0) { __threadfence(); atomicAdd(&g_chc[gX], 1u); }

            // --- logits_t = [h,ctx] @ Waf + bf ---
            if (w < 6) {
                float acc = 0.0f;
#pragma unroll
                for (int i = 0; i < 16; i++) {
                    int uu = lane + 32 * i;
                    acc += s_hc[uu] * s_waf[uu * 6 + w];
                }
#pragma unroll
                for (int o = 16; o; o >>= 1) acc += __shfl_down_sync(~0u, acc, o);
                if (!lane) out[((size_t)b * NSTEP + t) * 6 + w] = acc + bf[w];
            }
        }
    }
}

// ---------------- launch ----------------
extern "C" void kernel_launch(void* const* d_in, const int* in_sizes, int n_in,
                              void* d_out, int out_size) {
    const int*   ids  = (const int*)d_in[0];
    const float* mem  = (const float*)d_in[1];
    const float* eh   = (const float*)d_in[2];
    const float* ec   = (const float*)d_in[3];
    const float* Wi   = (const float*)d_in[4];
    const float* Wh   = (const float*)d_in[5];
    const float* bias = (const float*)d_in[6];
    const float* Wm   = (const float*)d_in[7];
    const float* Wq   = (const float*)d_in[8];
    const float* vv   = (const float*)d_in[9];
    const float* Wa   = (const float*)d_in[10];
    const float* Wf   = (const float*)d_in[11];
    const float* bf   = (const float*)d_in[12];
    float* out = (float*)d_out;

    static int smem_set = 0;
    if (!smem_set) {
        cudaFuncSetAttribute(k_loop, cudaFuncAttributeMaxDynamicSharedMemorySize, 41472);
        smem_set = 1;
    }

    k_p1<<<dim3(4096, 4), 256>>>(mem, Wm);
    k_p2<<<24576, 256>>>(mem);
    k_p3<<<588, 256>>>(Wa, Wi, Wh, Wq, Wf, eh);
    k_loop<<<256, 256, 41472>>>(ids, ec, Wi, Wh, bias, vv, bf, out);
}